// round 4
// baseline (speedup 1.0000x reference)
#include <cuda_runtime.h>
#include <cuda_bf16.h>
#include <float.h>
#include <math.h>

// Problem shape (fixed by reference setup_inputs)
#define B_   16
#define C_   256
#define H_   128
#define W_   128
#define HW_  (H_ * W_)           // 16384
#define HW4_ (HW_ / 4)           // 4096 float4 columns per image

// Scratch: feat [B, 2, H, W]  (avg then max)
__device__ float g_feat[B_ * 2 * HW_];
// Row-ready flags and consumed-counters, one per (image, row).
// Zero at module load; restored to zero by the consumed-count protocol at the
// end of every launch, so graph replays always start from a clean state.
__device__ int g_flag[B_ * H_];
__device__ int g_cnt [B_ * H_];

// ---------------------------------------------------------------------------
// Fused kernel: block (b, h) = one feat row.
//  Phase 1: channel mean+max over C=256 for the 128 pixels of row h
//           (256 thr = 32 float4 columns x 8 channel-splits), write feat row,
//           publish flag.
//  Phase 2: wait for rows h-1 / h+1 flags, then 3x3 conv + sigmoid for output
//           row h (center row from smem, neighbor rows from L2-hot g_feat).
//  Phase 3: consumed-count bookkeeping resets flags for the next launch.
// ---------------------------------------------------------------------------
__global__ __launch_bounds__(256) void fused_spatial_attention_kernel(
    const float* __restrict__ x,
    const float* __restrict__ conv_w,   // [1,2,3,3] OIHW
    float* __restrict__ out)            // [B,1,H,W]
{
    __shared__ float4 s_sum[256];
    __shared__ float4 s_max[256];
    __shared__ float  s_w[18];

    const int tid = threadIdx.x;
    const int col = tid & 31;                  // hw4 column within row
    const int cs  = tid >> 5;                  // channel split 0..7

    const int blk = blockIdx.x;                // 0..2047 == b*128 + h
    const int b   = blk >> 7;
    const int h   = blk & 127;
    const int hw4 = (h << 5) + col;            // row h, 32 float4 per row

    if (tid < 18) s_w[tid] = __ldg(conv_w + tid);

    // ---- Phase 1: reduction --------------------------------------------
    const float4* xb = reinterpret_cast<const float4*>(x)
                     + (size_t)b * C_ * HW4_ + (size_t)(cs * 32) * HW4_ + hw4;

    float4 s = make_float4(0.f, 0.f, 0.f, 0.f);
    float4 m = make_float4(-FLT_MAX, -FLT_MAX, -FLT_MAX, -FLT_MAX);

    #pragma unroll 8
    for (int c = 0; c < 32; ++c) {
        float4 v = __ldcs(xb + (size_t)c * HW4_);
        s.x += v.x; s.y += v.y; s.z += v.z; s.w += v.w;
        m.x = fmaxf(m.x, v.x); m.y = fmaxf(m.y, v.y);
        m.z = fmaxf(m.z, v.z); m.w = fmaxf(m.w, v.w);
    }

    s_sum[tid] = s;
    s_max[tid] = m;
    __syncthreads();

    if (tid < 32) {
        #pragma unroll
        for (int k = 1; k < 8; ++k) {
            float4 ps = s_sum[tid + k * 32];
            float4 pm = s_max[tid + k * 32];
            s.x += ps.x; s.y += ps.y; s.z += ps.z; s.w += ps.w;
            m.x = fmaxf(m.x, pm.x); m.y = fmaxf(m.y, pm.y);
            m.z = fmaxf(m.z, pm.z); m.w = fmaxf(m.w, pm.w);
        }
        const float inv = 1.0f / (float)C_;
        float4 a = make_float4(s.x * inv, s.y * inv, s.z * inv, s.w * inv);

        float4* fa = reinterpret_cast<float4*>(g_feat)
                   + (size_t)b * 2 * HW4_ + hw4;
        fa[0]    = a;   // channel 0: avg
        fa[HW4_] = m;   // channel 1: max

        // keep final row in smem for the conv center row
        s_sum[tid] = a;
        s_max[tid] = m;

        __threadfence();   // make feat row visible device-wide before flag
    }
    __syncthreads();

    if (tid == 0) atomicExch(&g_flag[blk], 1);

    // ---- Phase 2: wait on neighbor rows, then conv ----------------------
    if (tid == 0) {
        if (h > 0)
            while (atomicAdd(&g_flag[blk - 1], 0) == 0) __nanosleep(64);
        if (h < H_ - 1)
            while (atomicAdd(&g_flag[blk + 1], 0) == 0) __nanosleep(64);
        __threadfence();
    }
    __syncthreads();

    if (tid < W_) {
        const int w = tid;
        const float* s_avg = reinterpret_cast<const float*>(s_sum); // row h ch0
        const float* s_mx  = reinterpret_cast<const float*>(s_max); // row h ch1
        const float* fb    = g_feat + (size_t)b * 2 * HW_;

        float acc = 0.f;
        #pragma unroll
        for (int r = 0; r < 3; ++r) {
            const int hh = h + r - 1;
            if (hh < 0 || hh >= H_) continue;
            const float* r0;
            const float* r1;
            if (r == 1) { r0 = s_avg;            r1 = s_mx; }
            else        { r0 = fb + hh * W_;     r1 = r0 + HW_; }
            #pragma unroll
            for (int kw = 0; kw < 3; ++kw) {
                const int ww = w + kw - 1;
                if (ww < 0 || ww >= W_) continue;
                acc = fmaf(r0[ww], s_w[r * 3 + kw],     acc);
                acc = fmaf(r1[ww], s_w[9 + r * 3 + kw], acc);
            }
        }
        out[(size_t)b * HW_ + h * W_ + w] = 1.0f / (1.0f + __expf(-acc));
    }

    // ---- Phase 3: consumed-count bookkeeping (self-resetting flags) -----
    __syncthreads();   // all conv reads of feat rows are complete
    if (tid == 0) {
        #pragma unroll
        for (int dr = -1; dr <= 1; ++dr) {
            const int rh = h + dr;
            if (rh < 0 || rh >= H_) continue;
            const int r = b * H_ + rh;
            const int target = (rh == 0 || rh == H_ - 1) ? 2 : 3;
            if (atomicAdd(&g_cnt[r], 1) == target - 1) {
                // last consumer of row r this launch: reset for next launch
                atomicExch(&g_cnt[r], 0);
                atomicExch(&g_flag[r], 0);
            }
        }
    }
}

// ---------------------------------------------------------------------------
extern "C" void kernel_launch(void* const* d_in, const int* in_sizes, int n_in,
                              void* d_out, int out_size)
{
    const float* x      = (const float*)d_in[0];   // [16,256,128,128] f32
    const float* conv_w = (const float*)d_in[1];   // [1,2,3,3] f32
    float*       out    = (float*)d_out;           // [16,1,128,128] f32

    fused_spatial_attention_kernel<<<B_ * H_, 256>>>(x, conv_w, out);
}